// round 7
// baseline (speedup 1.0000x reference)
#include <cuda_runtime.h>
#include <cstdint>
#include <cstddef>

#define FEAT 128
#define NUM_BASES 4
#define NCT 5
#define MAX_NODES 100000

typedef unsigned int u32;

// scratch
__device__ float g_proj[(size_t)MAX_NODES * NUM_BASES * FEAT];
__device__ u32   g_wt_hi[NCT * FEAT * FEAT];   // [ct][n][k], tf32(hi) bits
__device__ u32   g_wt_lo[NCT * FEAT * FEAT];   // [ct][n][k], tf32(residual) bits

__device__ __forceinline__ u32 tf32r(float x) {
    u32 r; asm("cvt.rna.tf32.f32 %0, %1;" : "=r"(r) : "f"(x)); return r;
}
__device__ __forceinline__ void mma_tf32(float* d, const u32* a, const u32* b) {
    asm("mma.sync.aligned.m16n8k8.row.col.f32.tf32.tf32.f32 "
        "{%0,%1,%2,%3}, {%4,%5,%6,%7}, {%8,%9}, {%0,%1,%2,%3};"
        : "+f"(d[0]), "+f"(d[1]), "+f"(d[2]), "+f"(d[3])
        : "r"(a[0]), "r"(a[1]), "r"(a[2]), "r"(a[3]), "r"(b[0]), "r"(b[1]));
}
__device__ __forceinline__ u32 smem_u32(const void* p) {
    u32 a;
    asm("{ .reg .u64 t; cvta.to.shared.u64 t, %1; cvt.u32.u64 %0, t; }" : "=r"(a) : "l"(p));
    return a;
}
__device__ __forceinline__ void ldsm4(u32& r0, u32& r1, u32& r2, u32& r3, u32 addr) {
    asm volatile("ldmatrix.sync.aligned.m8n8.x4.shared.b16 {%0,%1,%2,%3}, [%4];"
                 : "=r"(r0), "=r"(r1), "=r"(r2), "=r"(r3) : "r"(addr));
}
__device__ __forceinline__ void cpa16(u32 dst, const void* src) {
    asm volatile("cp.async.ca.shared.global [%0], [%1], 16;" :: "r"(dst), "l"(src));
}
#define CPA_COMMIT() asm volatile("cp.async.commit_group;" ::: "memory")
#define CPA_WAIT(n)  asm volatile("cp.async.wait_group %0;" :: "n"(n) : "memory")

// ---------------- kernel 0: transpose + tf32-split weights ----------------
__global__ void transpose_w_kernel(const float* __restrict__ weight,
                                   const float* __restrict__ root)
{
    __shared__ float tile[32][33];
    const int ct = blockIdx.z;
    const float* __restrict__ src = (ct < NUM_BASES) ? (weight + (size_t)ct * FEAT * FEAT)
                                                     : root;
    const int n0 = blockIdx.x * 32, k0 = blockIdx.y * 32;
    const int tx = threadIdx.x, ty = threadIdx.y;  // 32 x 8
#pragma unroll
    for (int j = 0; j < 32; j += 8)
        tile[ty + j][tx] = src[(size_t)(k0 + ty + j) * FEAT + n0 + tx];
    __syncthreads();
    const size_t base = (size_t)ct * FEAT * FEAT;
#pragma unroll
    for (int j = 0; j < 32; j += 8) {
        const float x = tile[tx][ty + j];
        const u32 hi = tf32r(x);
        const float lo = x - __uint_as_float(hi);
        const size_t idx = base + (size_t)(n0 + ty + j) * FEAT + k0 + tx;
        g_wt_hi[idx] = hi;
        g_wt_lo[idx] = tf32r(lo);
    }
}

// ---------------- kernel 1: pipelined split-TF32 GEMM ----------------
// One block = 128 rows; loops ct = 0..4 (4 bases -> g_proj, root -> out+bias).
// A (hi/lo, full K) resident in smem; B streamed in 32-k chunks via cp.async.
#define APAD 132
#define BPAD 36
#define A_TILE_F (128 * APAD)      // 16896 floats
#define B_CHUNK_F (128 * BPAD)     // 4608 floats per (hi|lo) chunk
#define SM_TOTALB ((2 * A_TILE_F + 4 * B_CHUNK_F) * 4)  // 208896 B

__global__ void __launch_bounds__(256, 1)
rgcn_gemm_pipe_kernel(const float* __restrict__ h,
                      const float* __restrict__ bias,
                      float* __restrict__ out, int n_nodes)
{
    extern __shared__ float smem[];
    float* Ah = smem;
    float* Al = smem + A_TILE_F;
    float* Bbuf = smem + 2 * A_TILE_F;   // [buf][hi|lo][B_CHUNK_F]

    const int tid  = threadIdx.x;
    const int lane = tid & 31;
    const int w    = tid >> 5;
    const int g    = lane >> 2;
    const int tig  = lane & 3;
    const int warp_m = w & 3;        // 4 warps x 32 rows
    const int warp_n = w >> 2;       // 2 warps x 64 cols

    const int row0 = blockIdx.x * 128;

    const int a_row_in = lane & 15;
    const int a_kd     = (lane >> 4) * 4;
    const int b_row_in = (lane & 7) + ((lane >> 4) << 3);
    const int b_kd     = ((lane & 15) >> 3) * 4;

    const u32 sAh = smem_u32(Ah), sAl = smem_u32(Al);
    const u32 sB  = smem_u32(Bbuf);

    // ---- A producer: load once, split hi/lo ----
#pragma unroll
    for (int i = 0; i < 16; i++) {
        const int v  = tid + i * 256;
        const int r  = v >> 5;          // 0..127
        const int c4 = (v & 31) * 4;    // 0..124
        float4 av = make_float4(0.f, 0.f, 0.f, 0.f);
        const int gr = row0 + r;
        if (gr < n_nodes)
            av = *(const float4*)(h + (size_t)gr * FEAT + c4);
        u32 hi[4], lo[4];
#pragma unroll
        for (int e = 0; e < 4; e++) {
            const float x = (&av.x)[e];
            hi[e] = tf32r(x);
            lo[e] = tf32r(x - __uint_as_float(hi[e]));
        }
        *(uint4*)(Ah + r * APAD + c4) = make_uint4(hi[0], hi[1], hi[2], hi[3]);
        *(uint4*)(Al + r * APAD + c4) = make_uint4(lo[0], lo[1], lo[2], lo[3]);
    }

    // ---- B chunk issuer: 4 cp.async(16B) per matrix per thread ----
    auto issue_chunk = [&](int gi, int buf) {
        const int ct = gi >> 2, ch = gi & 3;
        const size_t gbase = (size_t)ct * FEAT * FEAT;
        float* dst_h = Bbuf + buf * 2 * B_CHUNK_F;
        float* dst_l = dst_h + B_CHUNK_F;
#pragma unroll
        for (int i = 0; i < 4; i++) {
            const int v = tid + i * 256;
            const int r = v >> 3;          // 0..127
            const int s4 = (v & 7) * 4;    // 0..28
            const size_t gi2 = gbase + (size_t)r * FEAT + ch * 32 + s4;
            const u32 doff = (u32)((r * BPAD + s4) * 4);
            cpa16(smem_u32(dst_h) + doff, g_wt_hi + gi2);
            cpa16(smem_u32(dst_l) + doff, g_wt_lo + gi2);
        }
        CPA_COMMIT();
    };

    issue_chunk(0, 0);

    float acc[2][8][4];
#pragma unroll
    for (int mi = 0; mi < 2; mi++)
#pragma unroll
        for (int j = 0; j < 8; j++)
#pragma unroll
            for (int c = 0; c < 4; c++) acc[mi][j][c] = 0.f;

    for (int ct = 0; ct < NCT; ct++) {
#pragma unroll 1
        for (int ch = 0; ch < 4; ch++) {
            const int gi = ct * 4 + ch;
            if (gi + 1 < 4 * NCT) {
                issue_chunk(gi + 1, (gi + 1) & 1);
                CPA_WAIT(1);
            } else {
                CPA_WAIT(0);
            }
            __syncthreads();

            const u32 sBh = sB + (u32)((gi & 1) * 2 * B_CHUNK_F * 4);
            const u32 sBl = sBh + (u32)(B_CHUNK_F * 4);

#pragma unroll
            for (int ks = 0; ks < 4; ks++) {
                const int kkA = ch * 32 + ks * 8;
                const int kkB = ks * 8;
                u32 ahi[2][4], alo[2][4];
#pragma unroll
                for (int mi = 0; mi < 2; mi++) {
                    const u32 off = (u32)(((warp_m * 32 + mi * 16 + a_row_in) * APAD
                                           + kkA + a_kd) * 4);
                    ldsm4(ahi[mi][0], ahi[mi][1], ahi[mi][2], ahi[mi][3], sAh + off);
                    ldsm4(alo[mi][0], alo[mi][1], alo[mi][2], alo[mi][3], sAl + off);
                }
                u32 bhi[8][2], blo[8][2];
#pragma unroll
                for (int jp = 0; jp < 4; jp++) {
                    const u32 off = (u32)(((warp_n * 64 + jp * 16 + b_row_in) * BPAD
                                           + kkB + b_kd) * 4);
                    ldsm4(bhi[2 * jp][0], bhi[2 * jp][1],
                          bhi[2 * jp + 1][0], bhi[2 * jp + 1][1], sBh + off);
                    ldsm4(blo[2 * jp][0], blo[2 * jp][1],
                          blo[2 * jp + 1][0], blo[2 * jp + 1][1], sBl + off);
                }
#pragma unroll
                for (int mi = 0; mi < 2; mi++)
#pragma unroll
                    for (int j = 0; j < 8; j++) {
                        mma_tf32(acc[mi][j], alo[mi], bhi[j]);
                        mma_tf32(acc[mi][j], ahi[mi], blo[j]);
                        mma_tf32(acc[mi][j], ahi[mi], bhi[j]);
                    }
            }
            __syncthreads();
        }

        // ---- epilogue for this ct (overlaps next ct's first prefetch) ----
#pragma unroll
        for (int mi = 0; mi < 2; mi++) {
#pragma unroll
            for (int half = 0; half < 2; half++) {
                const int grow = row0 + warp_m * 32 + mi * 16 + g + half * 8;
                if (grow < n_nodes) {
                    if (ct < NUM_BASES) {
                        float* p = g_proj + (size_t)grow * (NUM_BASES * FEAT)
                                 + ct * FEAT + warp_n * 64 + 2 * tig;
#pragma unroll
                        for (int j = 0; j < 8; j++)
                            *(float2*)(p + 8 * j) =
                                make_float2(acc[mi][j][2 * half], acc[mi][j][2 * half + 1]);
                    } else {
                        float* p = out + (size_t)grow * FEAT + warp_n * 64 + 2 * tig;
#pragma unroll
                        for (int j = 0; j < 8; j++) {
                            const float2 b =
                                *(const float2*)(bias + warp_n * 64 + 2 * tig + 8 * j);
                            *(float2*)(p + 8 * j) =
                                make_float2(acc[mi][j][2 * half] + b.x,
                                            acc[mi][j][2 * half + 1] + b.y);
                        }
                    }
                }
            }
        }
#pragma unroll
        for (int mi = 0; mi < 2; mi++)
#pragma unroll
            for (int j = 0; j < 8; j++)
#pragma unroll
                for (int c = 0; c < 4; c++) acc[mi][j][c] = 0.f;
    }
}

// ---------------- kernel 2: edge gather/combine/scatter ----------------
__global__ void rgcn_edge_kernel(const float* __restrict__ w_comp,
                                 const int* __restrict__ src,
                                 const int* __restrict__ dst,
                                 const int* __restrict__ rel,
                                 float* __restrict__ out, int n_edges)
{
    const int warp = (blockIdx.x * blockDim.x + threadIdx.x) >> 5;
    const int lane = threadIdx.x & 31;
    if (warp >= n_edges) return;

    const int s = src[warp];
    const int d = dst[warp];
    const int r = rel[warp];
    const float4 c = *(const float4*)(w_comp + r * NUM_BASES);

    const float* __restrict__ p = g_proj + (size_t)s * (NUM_BASES * FEAT);
    float* __restrict__ o = out + (size_t)d * FEAT;

#pragma unroll
    for (int j = 0; j < 4; j++) {
        const int i = lane + j * 32;
        float m = c.x * p[i]
                + c.y * p[FEAT + i]
                + c.z * p[2 * FEAT + i]
                + c.w * p[3 * FEAT + i];
        atomicAdd(o + i, m);
    }
}

__global__ void rgcn_relu_kernel(float* __restrict__ out, int n4)
{
    int i = blockIdx.x * blockDim.x + threadIdx.x;
    if (i < n4) {
        float4 v = ((float4*)out)[i];
        v.x = fmaxf(v.x, 0.f); v.y = fmaxf(v.y, 0.f);
        v.z = fmaxf(v.z, 0.f); v.w = fmaxf(v.w, 0.f);
        ((float4*)out)[i] = v;
    }
}

extern "C" void kernel_launch(void* const* d_in, const int* in_sizes, int n_in,
                              void* d_out, int out_size)
{
    const float* h      = (const float*)d_in[0];
    const float* weight = (const float*)d_in[1];
    const float* w_comp = (const float*)d_in[2];
    const float* root   = (const float*)d_in[3];
    const float* bias   = (const float*)d_in[4];
    const int*   src    = (const int*)d_in[5];
    const int*   dst    = (const int*)d_in[6];
    const int*   rel    = (const int*)d_in[7];

    const int n_nodes = in_sizes[0] / FEAT;
    const int n_edges = in_sizes[5];
    float* out = (float*)d_out;

    cudaFuncSetAttribute(rgcn_gemm_pipe_kernel,
                         cudaFuncAttributeMaxDynamicSharedMemorySize, SM_TOTALB);

    // 0) transpose + tf32-split weights (tiny)
    dim3 gt(4, 4, NCT);
    transpose_w_kernel<<<gt, dim3(32, 8)>>>(weight, root);

    // 1) pipelined split-TF32 GEMM: proj (4 bases) + root+bias into out
    rgcn_gemm_pipe_kernel<<<(n_nodes + 127) / 128, 256, SM_TOTALB>>>(h, bias, out, n_nodes);

    // 2) edge combine + scatter-add
    int blocks_e = (n_edges + 7) / 8;
    rgcn_edge_kernel<<<blocks_e, 256>>>(w_comp, src, dst, rel, out, n_edges);

    // 3) ReLU
    int n4 = out_size / 4;
    rgcn_relu_kernel<<<(n4 + 255) / 256, 256>>>(out, n4);
}